// round 1
// baseline (speedup 1.0000x reference)
#include <cuda_runtime.h>

#define BATCH 2
#define SEQ 4096
#define NH 16
#define DK 64
#define DM 1024
#define L2E 1.4426950408889634f

// ---------------- scratch (no allocation allowed) ----------------
__device__ float g_Q[(size_t)BATCH * NH * SEQ * DK];
__device__ float g_K[(size_t)BATCH * NH * SEQ * DK];
__device__ float g_V[(size_t)BATCH * NH * SEQ * DK];
__device__ float g_A[(size_t)BATCH * SEQ * DM];

// ---------------- GEMM: C = A(M x 1024) * W(1024 x 1024)^T ----------------
// MODE 0: plain row-major C[M][1024]
// MODE 1: scatter to [b][h][s][64] (for Q/K/V)
template <int MODE>
__global__ __launch_bounds__(256) void gemm_kernel(const float* __restrict__ A,
                                                   const float* __restrict__ W,
                                                   float* __restrict__ C) {
    __shared__ float As[16 * 64];
    __shared__ float Bs[16 * 64];

    const int t  = threadIdx.x;
    const int tr = t >> 4;      // 0..15  (row group)
    const int tc = t & 15;      // 0..15  (col group)
    const int m0 = blockIdx.y * 64;
    const int n0 = blockIdx.x * 64;

    const int lm = t & 63;      // tile row loaded by this thread
    const int lq = t >> 6;      // which float4 along k (0..3)

    const float* Ap = A + (size_t)(m0 + lm) * DM + lq * 4;
    const float* Wp = W + (size_t)(n0 + lm) * DM + lq * 4;

    float acc[4][4];
#pragma unroll
    for (int i = 0; i < 4; i++)
#pragma unroll
        for (int j = 0; j < 4; j++) acc[i][j] = 0.f;

    for (int kb = 0; kb < DM; kb += 16) {
        float4 a = *(const float4*)(Ap + kb);
        float4 w = *(const float4*)(Wp + kb);
        As[(lq * 4 + 0) * 64 + lm] = a.x;
        As[(lq * 4 + 1) * 64 + lm] = a.y;
        As[(lq * 4 + 2) * 64 + lm] = a.z;
        As[(lq * 4 + 3) * 64 + lm] = a.w;
        Bs[(lq * 4 + 0) * 64 + lm] = w.x;
        Bs[(lq * 4 + 1) * 64 + lm] = w.y;
        Bs[(lq * 4 + 2) * 64 + lm] = w.z;
        Bs[(lq * 4 + 3) * 64 + lm] = w.w;
        __syncthreads();

#pragma unroll
        for (int k = 0; k < 16; k++) {
            float4 av = *(const float4*)&As[k * 64 + tr * 4];
            float4 bv = *(const float4*)&Bs[k * 64 + tc * 4];
            float ar[4] = {av.x, av.y, av.z, av.w};
            float br[4] = {bv.x, bv.y, bv.z, bv.w};
#pragma unroll
            for (int i = 0; i < 4; i++)
#pragma unroll
                for (int j = 0; j < 4; j++)
                    acc[i][j] = fmaf(ar[i], br[j], acc[i][j]);
        }
        __syncthreads();
    }

    if (MODE == 0) {
#pragma unroll
        for (int i = 0; i < 4; i++) {
            int m = m0 + tr * 4 + i;
            float4 o = make_float4(acc[i][0], acc[i][1], acc[i][2], acc[i][3]);
            *(float4*)&C[(size_t)m * DM + n0 + tc * 4] = o;
        }
    } else {
        const int n = n0 + tc * 4;
        const int h = n >> 6;
        const int d = n & 63;
#pragma unroll
        for (int i = 0; i < 4; i++) {
            int m = m0 + tr * 4 + i;
            int b = m >> 12;
            int s = m & (SEQ - 1);
            float4 o = make_float4(acc[i][0], acc[i][1], acc[i][2], acc[i][3]);
            *(float4*)&C[((size_t)(b * NH + h) * SEQ + s) * DK + d] = o;
        }
    }
}

// ---------------- RoPE (in-place on g_Q / g_K) ----------------
__global__ void rope_kernel(float* __restrict__ Q, float* __restrict__ K,
                            const int* __restrict__ pos) {
    const int NPAIR = BATCH * NH * SEQ * (DK / 2);  // 4194304
    int i = blockIdx.x * blockDim.x + threadIdx.x;
    if (i >= NPAIR) return;
    int j = i & 31;
    int s = (i >> 5) & (SEQ - 1);
    int h = (i >> 17) & (NH - 1);
    int b = i >> 21;

    float* ptr = blockIdx.y ? K : Q;
    int p = pos[b * SEQ + s];
    // freq_j = 10000^(-j/32) = 2^(-j * log2(10000)/32)
    float freq = exp2f(-(float)j * (13.287712379549449f / 32.f));
    float ang = (float)p * freq;
    float sn, cs;
    sincosf(ang, &sn, &cs);

    size_t base = ((size_t)(b * NH + h) * SEQ + s) * DK + 2 * j;
    float e = ptr[base];
    float o = ptr[base + 1];
    ptr[base]     = e * cs - o * sn;
    ptr[base + 1] = e * sn + o * cs;
}

// ---------------- causal flash attention ----------------
// grid (64 q-tiles, 16 heads, 2 batch); 256 threads; 4x4 micro-tiles.
// smem (dynamic, 69632 B): QsT[64k][68], KsT[64k][68], Vs[64c][68], PsT[64c][68]
__global__ __launch_bounds__(256) void attn_kernel(const float* __restrict__ gQ,
                                                   const float* __restrict__ gK,
                                                   const float* __restrict__ gV,
                                                   float* __restrict__ gO) {
    extern __shared__ float sm[];
    float* QsT = sm;                // [k][r] stride 68
    float* KsT = sm + 64 * 68;      // [k][c]
    float* Vs  = sm + 2 * 64 * 68;  // [c][d]
    float* PsT = sm + 3 * 64 * 68;  // [c][r]

    const int qt = 63 - (int)blockIdx.x;   // big tiles first
    const int h  = blockIdx.y;
    const int b  = blockIdx.z;
    const int t  = threadIdx.x;
    const int tr = t >> 4;
    const int tc = t & 15;

    const size_t bh = (size_t)(b * NH + h) * SEQ;
    const float* Qb = gQ + (bh + qt * 64) * DK;
    const float* Kb = gK + bh * DK;
    const float* Vb = gV + bh * DK;

    const int lr = t & 63;
    const int lq = t >> 6;

    // load Q tile transposed + pre-scale by (1/sqrt(dk)) * log2(e)
    const float qscale = 0.125f * L2E;
#pragma unroll
    for (int i = 0; i < 4; i++) {
        int f = lq * 4 + i;
        float4 v = *(const float4*)(Qb + (size_t)lr * DK + f * 4);
        QsT[(f * 4 + 0) * 68 + lr] = v.x * qscale;
        QsT[(f * 4 + 1) * 68 + lr] = v.y * qscale;
        QsT[(f * 4 + 2) * 68 + lr] = v.z * qscale;
        QsT[(f * 4 + 3) * 68 + lr] = v.w * qscale;
    }

    float m_i[4], l_i[4], acc[4][4];
#pragma unroll
    for (int i = 0; i < 4; i++) {
        m_i[i] = -1e30f;
        l_i[i] = 0.f;
#pragma unroll
        for (int j = 0; j < 4; j++) acc[i][j] = 0.f;
    }

    const int ntiles = qt + 1;
    for (int kt = 0; kt < ntiles; kt++) {
        // load K (transposed) and V tiles
#pragma unroll
        for (int i = 0; i < 4; i++) {
            int f = lq * 4 + i;
            const float* kp = Kb + (size_t)(kt * 64 + lr) * DK + f * 4;
            float4 kv = *(const float4*)kp;
            KsT[(f * 4 + 0) * 68 + lr] = kv.x;
            KsT[(f * 4 + 1) * 68 + lr] = kv.y;
            KsT[(f * 4 + 2) * 68 + lr] = kv.z;
            KsT[(f * 4 + 3) * 68 + lr] = kv.w;
            const float* vp = Vb + (size_t)(kt * 64 + lr) * DK + f * 4;
            *(float4*)&Vs[lr * 68 + f * 4] = *(const float4*)vp;
        }
        __syncthreads();

        // S = Q K^T (pre-scaled, base-2 domain)
        float s[4][4];
#pragma unroll
        for (int i = 0; i < 4; i++)
#pragma unroll
            for (int j = 0; j < 4; j++) s[i][j] = 0.f;

#pragma unroll 16
        for (int k = 0; k < 64; k++) {
            float4 qv = *(const float4*)&QsT[k * 68 + tr * 4];
            float4 kv = *(const float4*)&KsT[k * 68 + tc * 4];
            float qr[4] = {qv.x, qv.y, qv.z, qv.w};
            float kr[4] = {kv.x, kv.y, kv.z, kv.w};
#pragma unroll
            for (int i = 0; i < 4; i++)
#pragma unroll
                for (int j = 0; j < 4; j++)
                    s[i][j] = fmaf(qr[i], kr[j], s[i][j]);
        }

        if (kt == qt) {  // causal mask within diagonal tile
#pragma unroll
            for (int i = 0; i < 4; i++)
#pragma unroll
                for (int j = 0; j < 4; j++)
                    if (tc * 4 + j > tr * 4 + i) s[i][j] = -1e30f;
        }

        // online softmax per row (rows owned by 16 lanes sharing tr)
#pragma unroll
        for (int i = 0; i < 4; i++) {
            float tm = fmaxf(fmaxf(s[i][0], s[i][1]), fmaxf(s[i][2], s[i][3]));
            tm = fmaxf(tm, __shfl_xor_sync(0xffffffffu, tm, 1));
            tm = fmaxf(tm, __shfl_xor_sync(0xffffffffu, tm, 2));
            tm = fmaxf(tm, __shfl_xor_sync(0xffffffffu, tm, 4));
            tm = fmaxf(tm, __shfl_xor_sync(0xffffffffu, tm, 8));
            float mn = fmaxf(m_i[i], tm);
            float alpha = exp2f(m_i[i] - mn);
            m_i[i] = mn;
            float rs = 0.f;
#pragma unroll
            for (int j = 0; j < 4; j++) {
                s[i][j] = exp2f(s[i][j] - mn);
                rs += s[i][j];
            }
            rs += __shfl_xor_sync(0xffffffffu, rs, 1);
            rs += __shfl_xor_sync(0xffffffffu, rs, 2);
            rs += __shfl_xor_sync(0xffffffffu, rs, 4);
            rs += __shfl_xor_sync(0xffffffffu, rs, 8);
            l_i[i] = l_i[i] * alpha + rs;
#pragma unroll
            for (int j = 0; j < 4; j++) acc[i][j] *= alpha;
        }

        // publish P transposed: PsT[c][r]
#pragma unroll
        for (int j = 0; j < 4; j++) {
            float4 pv = make_float4(s[0][j], s[1][j], s[2][j], s[3][j]);
            *(float4*)&PsT[(tc * 4 + j) * 68 + tr * 4] = pv;
        }
        __syncthreads();

        // acc += P V
#pragma unroll 16
        for (int c = 0; c < 64; c++) {
            float4 pv = *(const float4*)&PsT[c * 68 + tr * 4];
            float4 vv = *(const float4*)&Vs[c * 68 + tc * 4];
            float pr[4] = {pv.x, pv.y, pv.z, pv.w};
            float vr[4] = {vv.x, vv.y, vv.z, vv.w};
#pragma unroll
            for (int i = 0; i < 4; i++)
#pragma unroll
                for (int j = 0; j < 4; j++)
                    acc[i][j] = fmaf(pr[i], vr[j], acc[i][j]);
        }
        __syncthreads();
    }

    // normalize and write out in [b][s][h][d]
#pragma unroll
    for (int i = 0; i < 4; i++) {
        float inv = 1.f / l_i[i];
        int sg = qt * 64 + tr * 4 + i;
        float4 o = make_float4(acc[i][0] * inv, acc[i][1] * inv,
                               acc[i][2] * inv, acc[i][3] * inv);
        *(float4*)&gO[(((size_t)b * SEQ + sg) * NH + h) * DK + tc * 4] = o;
    }
}

// ---------------- launch ----------------
extern "C" void kernel_launch(void* const* d_in, const int* in_sizes, int n_in,
                              void* d_out, int out_size) {
    const float* x   = (const float*)d_in[0];
    const int* tpos  = (const int*)d_in[1];
    const float* Wq  = (const float*)d_in[2];
    const float* Wk  = (const float*)d_in[3];
    const float* Wv  = (const float*)d_in[4];
    const float* Wo  = (const float*)d_in[5];
    float* out       = (float*)d_out;

    float *gQ, *gK, *gV, *gA;
    cudaGetSymbolAddress((void**)&gQ, g_Q);
    cudaGetSymbolAddress((void**)&gK, g_K);
    cudaGetSymbolAddress((void**)&gV, g_V);
    cudaGetSymbolAddress((void**)&gA, g_A);

    dim3 gg(DM / 64, (BATCH * SEQ) / 64);  // (16, 128)

    gemm_kernel<1><<<gg, 256>>>(x, Wq, gQ);
    gemm_kernel<1><<<gg, 256>>>(x, Wk, gK);
    gemm_kernel<1><<<gg, 256>>>(x, Wv, gV);

    const int NPAIR = BATCH * NH * SEQ * (DK / 2);
    rope_kernel<<<dim3((NPAIR + 255) / 256, 2), 256>>>(gQ, gK, tpos);

    const int ATT_SMEM = 4 * 64 * 68 * (int)sizeof(float);  // 69632
    cudaFuncSetAttribute(attn_kernel, cudaFuncAttributeMaxDynamicSharedMemorySize,
                         ATT_SMEM);
    attn_kernel<<<dim3(SEQ / 64, NH, BATCH), 256, ATT_SMEM>>>(gQ, gK, gV, gA);

    gemm_kernel<0><<<gg, 256>>>(gA, Wo, out);
}

// round 3
// speedup vs baseline: 3.9984x; 3.9984x over previous
#include <cuda_runtime.h>
#include <cstdint>

#define BATCH 2
#define SEQ 4096
#define NH 16
#define DK 64
#define DM 1024
#define L2E 1.4426950408889634f

// ---------------- scratch (no allocation allowed) ----------------
__device__ float g_Q[(size_t)BATCH * NH * SEQ * DK];
__device__ float g_K[(size_t)BATCH * NH * SEQ * DK];
__device__ float g_V[(size_t)BATCH * NH * SEQ * DK];
__device__ float g_A[(size_t)BATCH * SEQ * DM];

__device__ __forceinline__ uint32_t f2tf(float x) {
    uint32_t r;
    asm("cvt.rna.tf32.f32 %0, %1;" : "=r"(r) : "f"(x));
    return r;
}

__device__ __forceinline__ void mma_tf32(float c[4], uint32_t a0, uint32_t a1,
                                         uint32_t a2, uint32_t a3,
                                         uint32_t b0, uint32_t b1) {
    asm volatile(
        "mma.sync.aligned.m16n8k8.row.col.f32.tf32.tf32.f32 "
        "{%0,%1,%2,%3}, {%4,%5,%6,%7}, {%8,%9}, {%0,%1,%2,%3};"
        : "+f"(c[0]), "+f"(c[1]), "+f"(c[2]), "+f"(c[3])
        : "r"(a0), "r"(a1), "r"(a2), "r"(a3), "r"(b0), "r"(b1));
}

// ---------------- GEMM: C = A(M x 1024) * W(1024 x 1024)^T, tf32 tensor ----
// MODE 0: row-major C[M][1024];  MODE 1: scatter to [b][h][s][64]
template <int MODE>
__global__ __launch_bounds__(256) void gemm_tf32(const float* __restrict__ A,
                                                 const float* __restrict__ W,
                                                 float* __restrict__ C) {
    __shared__ uint32_t As[128 * 36];
    __shared__ uint32_t Ws[128 * 36];

    const int tid = threadIdx.x;
    const int wid = tid >> 5, lane = tid & 31;
    const int g = lane >> 2, tig = lane & 3;
    const int wm = (wid & 1) * 64, wn = (wid >> 1) * 32;
    const int m0 = blockIdx.y * 128, n0 = blockIdx.x * 128;
    const int lrow = tid >> 3, lc4 = (tid & 7) * 4;

    float acc[4][4][4];
#pragma unroll
    for (int mt = 0; mt < 4; mt++)
#pragma unroll
        for (int nt = 0; nt < 4; nt++)
#pragma unroll
            for (int k = 0; k < 4; k++) acc[mt][nt][k] = 0.f;

    for (int kb = 0; kb < DM; kb += 32) {
#pragma unroll
        for (int p = 0; p < 4; p++) {
            int r = lrow + p * 32;
            float4 av = *(const float4*)(A + (size_t)(m0 + r) * DM + kb + lc4);
            float4 wv = *(const float4*)(W + (size_t)(n0 + r) * DM + kb + lc4);
            uint32_t* ap = &As[r * 36 + lc4];
            ap[0] = f2tf(av.x); ap[1] = f2tf(av.y);
            ap[2] = f2tf(av.z); ap[3] = f2tf(av.w);
            uint32_t* wp = &Ws[r * 36 + lc4];
            wp[0] = f2tf(wv.x); wp[1] = f2tf(wv.y);
            wp[2] = f2tf(wv.z); wp[3] = f2tf(wv.w);
        }
        __syncthreads();

#pragma unroll
        for (int kk = 0; kk < 32; kk += 8) {
            uint32_t a[4][4], b[4][2];
#pragma unroll
            for (int mt = 0; mt < 4; mt++) {
                int r = wm + mt * 16;
                a[mt][0] = As[(r + g) * 36 + kk + tig];
                a[mt][1] = As[(r + g + 8) * 36 + kk + tig];
                a[mt][2] = As[(r + g) * 36 + kk + tig + 4];
                a[mt][3] = As[(r + g + 8) * 36 + kk + tig + 4];
            }
#pragma unroll
            for (int nt = 0; nt < 4; nt++) {
                int cn = wn + nt * 8 + g;
                b[nt][0] = Ws[cn * 36 + kk + tig];
                b[nt][1] = Ws[cn * 36 + kk + tig + 4];
            }
#pragma unroll
            for (int mt = 0; mt < 4; mt++)
#pragma unroll
                for (int nt = 0; nt < 4; nt++)
                    mma_tf32(acc[mt][nt], a[mt][0], a[mt][1], a[mt][2], a[mt][3],
                             b[nt][0], b[nt][1]);
        }
        __syncthreads();
    }

#pragma unroll
    for (int mt = 0; mt < 4; mt++) {
#pragma unroll
        for (int nt = 0; nt < 4; nt++) {
            int r0 = m0 + wm + mt * 16 + g;
            int r1 = r0 + 8;
            int cc = n0 + wn + nt * 8 + 2 * tig;
            if (MODE == 0) {
                *(float2*)&C[(size_t)r0 * DM + cc] =
                    make_float2(acc[mt][nt][0], acc[mt][nt][1]);
                *(float2*)&C[(size_t)r1 * DM + cc] =
                    make_float2(acc[mt][nt][2], acc[mt][nt][3]);
            } else {
                int h = cc >> 6, d = cc & 63;
                int b0i = r0 >> 12, s0 = r0 & (SEQ - 1);
                int b1i = r1 >> 12, s1 = r1 & (SEQ - 1);
                *(float2*)&C[((size_t)(b0i * NH + h) * SEQ + s0) * DK + d] =
                    make_float2(acc[mt][nt][0], acc[mt][nt][1]);
                *(float2*)&C[((size_t)(b1i * NH + h) * SEQ + s1) * DK + d] =
                    make_float2(acc[mt][nt][2], acc[mt][nt][3]);
            }
        }
    }
}

// ---------------- RoPE (in-place on g_Q / g_K) ----------------
__global__ void rope_kernel(float* __restrict__ Q, float* __restrict__ K,
                            const int* __restrict__ pos) {
    const int NPAIR = BATCH * NH * SEQ * (DK / 2);
    int i = blockIdx.x * blockDim.x + threadIdx.x;
    if (i >= NPAIR) return;
    int j = i & 31;
    int s = (i >> 5) & (SEQ - 1);
    int h = (i >> 17) & (NH - 1);
    int b = i >> 21;

    float* ptr = blockIdx.y ? K : Q;
    int p = pos[b * SEQ + s];
    float freq = exp2f(-(float)j * (13.287712379549449f / 32.f));
    float ang = (float)p * freq;
    float sn, cs;
    sincosf(ang, &sn, &cs);

    size_t base = ((size_t)(b * NH + h) * SEQ + s) * DK + 2 * j;
    float e = ptr[base];
    float o = ptr[base + 1];
    ptr[base] = e * cs - o * sn;
    ptr[base + 1] = e * sn + o * cs;
}

// ---------------- causal flash attention, tf32 mma ----------------
// grid (64 q-tiles, 16 heads, 2 batch); 128 threads = 4 warps x 16 rows.
// smem (dynamic): Qs[64][68], Ks[64][68], Vs[64][72], Ps[64][68]  (tf32 u32)
#define ATT_SMEM ((64 * 68 + 64 * 68 + 64 * 72 + 64 * 68) * 4)

__global__ __launch_bounds__(128) void attn_tf32(const float* __restrict__ gQ,
                                                 const float* __restrict__ gK,
                                                 const float* __restrict__ gV,
                                                 float* __restrict__ gO) {
    extern __shared__ uint32_t sm[];
    uint32_t* Qs = sm;                 // [r][k] stride 68
    uint32_t* Ks = Qs + 64 * 68;       // [n][k] stride 68
    uint32_t* Vs = Ks + 64 * 68;       // [c][d] stride 72
    uint32_t* Ps = Vs + 64 * 72;       // [r][c] stride 68

    const int qt = 63 - (int)blockIdx.x;
    const int h = blockIdx.y;
    const int b = blockIdx.z;
    const int tid = threadIdx.x;
    const int wid = tid >> 5, lane = tid & 31;
    const int g = lane >> 2, tig = lane & 3;
    const int wr = wid * 16;

    const size_t bh = (size_t)(b * NH + h) * SEQ;
    const float* Qb = gQ + (bh + (size_t)qt * 64) * DK;
    const float* Kb = gK + bh * DK;
    const float* Vb = gV + bh * DK;

    const float qscale = 0.125f * L2E;

    // load Q tile (scaled, tf32)
#pragma unroll
    for (int p = 0; p < 8; p++) {
        int idx = p * 128 + tid;
        int r = idx >> 4, c4 = (idx & 15) * 4;
        float4 v = *(const float4*)(Qb + (size_t)r * DK + c4);
        uint32_t* qp = &Qs[r * 68 + c4];
        qp[0] = f2tf(v.x * qscale); qp[1] = f2tf(v.y * qscale);
        qp[2] = f2tf(v.z * qscale); qp[3] = f2tf(v.w * qscale);
    }

    float oacc[8][4];
    float m0 = -1e30f, m1 = -1e30f, l0 = 0.f, l1 = 0.f;
#pragma unroll
    for (int nt = 0; nt < 8; nt++)
#pragma unroll
        for (int k = 0; k < 4; k++) oacc[nt][k] = 0.f;

    const int ntiles = qt + 1;
    for (int kt = 0; kt < ntiles; kt++) {
        __syncthreads();
        // load K (stride 68) and V (stride 72) tiles
#pragma unroll
        for (int p = 0; p < 8; p++) {
            int idx = p * 128 + tid;
            int r = idx >> 4, c4 = (idx & 15) * 4;
            float4 kv = *(const float4*)(Kb + (size_t)(kt * 64 + r) * DK + c4);
            uint32_t* kp = &Ks[r * 68 + c4];
            kp[0] = f2tf(kv.x); kp[1] = f2tf(kv.y);
            kp[2] = f2tf(kv.z); kp[3] = f2tf(kv.w);
            float4 vv = *(const float4*)(Vb + (size_t)(kt * 64 + r) * DK + c4);
            uint32_t* vp = &Vs[r * 72 + c4];
            vp[0] = f2tf(vv.x); vp[1] = f2tf(vv.y);
            vp[2] = f2tf(vv.z); vp[3] = f2tf(vv.w);
        }
        __syncthreads();

        // S = Q K^T (pre-scaled, base-2)
        float sacc[8][4];
#pragma unroll
        for (int nt = 0; nt < 8; nt++)
#pragma unroll
            for (int k = 0; k < 4; k++) sacc[nt][k] = 0.f;

#pragma unroll
        for (int kk = 0; kk < 64; kk += 8) {
            uint32_t a0 = Qs[(wr + g) * 68 + kk + tig];
            uint32_t a1 = Qs[(wr + g + 8) * 68 + kk + tig];
            uint32_t a2 = Qs[(wr + g) * 68 + kk + tig + 4];
            uint32_t a3 = Qs[(wr + g + 8) * 68 + kk + tig + 4];
#pragma unroll
            for (int nt = 0; nt < 8; nt++) {
                uint32_t b0 = Ks[(nt * 8 + g) * 68 + kk + tig];
                uint32_t b1 = Ks[(nt * 8 + g) * 68 + kk + tig + 4];
                mma_tf32(sacc[nt], a0, a1, a2, a3, b0, b1);
            }
        }

        if (kt == qt) {  // causal mask on diagonal tile
#pragma unroll
            for (int nt = 0; nt < 8; nt++) {
                int c0 = nt * 8 + 2 * tig, c1 = c0 + 1;
                if (c0 > wr + g) sacc[nt][0] = -1e30f;
                if (c1 > wr + g) sacc[nt][1] = -1e30f;
                if (c0 > wr + g + 8) sacc[nt][2] = -1e30f;
                if (c1 > wr + g + 8) sacc[nt][3] = -1e30f;
            }
        }

        // online softmax; rows (wr+g) and (wr+g+8)
        float tm0 = -1e30f, tm1 = -1e30f;
#pragma unroll
        for (int nt = 0; nt < 8; nt++) {
            tm0 = fmaxf(tm0, fmaxf(sacc[nt][0], sacc[nt][1]));
            tm1 = fmaxf(tm1, fmaxf(sacc[nt][2], sacc[nt][3]));
        }
        tm0 = fmaxf(tm0, __shfl_xor_sync(0xffffffffu, tm0, 1));
        tm0 = fmaxf(tm0, __shfl_xor_sync(0xffffffffu, tm0, 2));
        tm1 = fmaxf(tm1, __shfl_xor_sync(0xffffffffu, tm1, 1));
        tm1 = fmaxf(tm1, __shfl_xor_sync(0xffffffffu, tm1, 2));

        float mn0 = fmaxf(m0, tm0), mn1 = fmaxf(m1, tm1);
        float al0 = exp2f(m0 - mn0), al1 = exp2f(m1 - mn1);
        m0 = mn0; m1 = mn1;

        float rs0 = 0.f, rs1 = 0.f;
#pragma unroll
        for (int nt = 0; nt < 8; nt++) {
            sacc[nt][0] = exp2f(sacc[nt][0] - mn0);
            sacc[nt][1] = exp2f(sacc[nt][1] - mn0);
            sacc[nt][2] = exp2f(sacc[nt][2] - mn1);
            sacc[nt][3] = exp2f(sacc[nt][3] - mn1);
            rs0 += sacc[nt][0] + sacc[nt][1];
            rs1 += sacc[nt][2] + sacc[nt][3];
        }
        rs0 += __shfl_xor_sync(0xffffffffu, rs0, 1);
        rs0 += __shfl_xor_sync(0xffffffffu, rs0, 2);
        rs1 += __shfl_xor_sync(0xffffffffu, rs1, 1);
        rs1 += __shfl_xor_sync(0xffffffffu, rs1, 2);
        l0 = l0 * al0 + rs0;
        l1 = l1 * al1 + rs1;

#pragma unroll
        for (int nt = 0; nt < 8; nt++) {
            oacc[nt][0] *= al0; oacc[nt][1] *= al0;
            oacc[nt][2] *= al1; oacc[nt][3] *= al1;
        }

        // publish P (tf32) to smem rows owned by this warp
#pragma unroll
        for (int nt = 0; nt < 8; nt++) {
            uint2 p0 = make_uint2(f2tf(sacc[nt][0]), f2tf(sacc[nt][1]));
            uint2 p1 = make_uint2(f2tf(sacc[nt][2]), f2tf(sacc[nt][3]));
            *(uint2*)&Ps[(wr + g) * 68 + nt * 8 + 2 * tig] = p0;
            *(uint2*)&Ps[(wr + g + 8) * 68 + nt * 8 + 2 * tig] = p1;
        }
        __syncwarp();

        // O += P V
#pragma unroll
        for (int kk = 0; kk < 64; kk += 8) {
            uint32_t a0 = Ps[(wr + g) * 68 + kk + tig];
            uint32_t a1 = Ps[(wr + g + 8) * 68 + kk + tig];
            uint32_t a2 = Ps[(wr + g) * 68 + kk + tig + 4];
            uint32_t a3 = Ps[(wr + g + 8) * 68 + kk + tig + 4];
#pragma unroll
            for (int nt = 0; nt < 8; nt++) {
                uint32_t b0 = Vs[(kk + tig) * 72 + nt * 8 + g];
                uint32_t b1 = Vs[(kk + tig + 4) * 72 + nt * 8 + g];
                mma_tf32(oacc[nt], a0, a1, a2, a3, b0, b1);
            }
        }
    }

    // normalize + write out [b][s][h][d]
    float inv0 = 1.f / l0, inv1 = 1.f / l1;
    int sg0 = qt * 64 + wr + g, sg1 = sg0 + 8;
#pragma unroll
    for (int nt = 0; nt < 8; nt++) {
        int d = nt * 8 + 2 * tig;
        *(float2*)&gO[(((size_t)b * SEQ + sg0) * NH + h) * DK + d] =
            make_float2(oacc[nt][0] * inv0, oacc[nt][1] * inv0);
        *(float2*)&gO[(((size_t)b * SEQ + sg1) * NH + h) * DK + d] =
            make_float2(oacc[nt][2] * inv1, oacc[nt][3] * inv1);
    }
}

// ---------------- launch ----------------
extern "C" void kernel_launch(void* const* d_in, const int* in_sizes, int n_in,
                              void* d_out, int out_size) {
    const float* x = (const float*)d_in[0];
    const int* tpos = (const int*)d_in[1];
    const float* Wq = (const float*)d_in[2];
    const float* Wk = (const float*)d_in[3];
    const float* Wv = (const float*)d_in[4];
    const float* Wo = (const float*)d_in[5];
    float* out = (float*)d_out;

    float *gQ, *gK, *gV, *gA;
    cudaGetSymbolAddress((void**)&gQ, g_Q);
    cudaGetSymbolAddress((void**)&gK, g_K);
    cudaGetSymbolAddress((void**)&gV, g_V);
    cudaGetSymbolAddress((void**)&gA, g_A);

    dim3 gg(DM / 128, (BATCH * SEQ) / 128);  // (8, 64)

    gemm_tf32<1><<<gg, 256>>>(x, Wq, gQ);
    gemm_tf32<1><<<gg, 256>>>(x, Wk, gK);
    gemm_tf32<1><<<gg, 256>>>(x, Wv, gV);

    const int NPAIR = BATCH * NH * SEQ * (DK / 2);
    rope_kernel<<<dim3((NPAIR + 255) / 256, 2), 256>>>(gQ, gK, tpos);

    cudaFuncSetAttribute(attn_tf32, cudaFuncAttributeMaxDynamicSharedMemorySize,
                         ATT_SMEM);
    attn_tf32<<<dim3(SEQ / 64, NH, BATCH), 128, ATT_SMEM>>>(gQ, gK, gV, gA);

    gemm_tf32<0><<<gg, 256>>>(gA, Wo, out);
}